// round 3
// baseline (speedup 1.0000x reference)
#include <cuda_runtime.h>

// SSIM loss — separable 11-tap Gaussian, fused single-kernel (conv + SSIM +
// grid reduction via last-block-done). f32x2 packed FMA.
// pred/target: [64,3,256,256] f32; window = outer(g,g); out scalar f32.

#define TW 32
#define TH 64
#define HALO 5
#define IN_W 42          // TW + 10
#define IN_H 74          // TH + 10
#define PS 43            // p/t smem row stride (floats) — conflict-free
#define IMG_H 256
#define IMG_W 256
#define NIMG 192
#define TX 8
#define TY 4
#define NBLOCKS (NIMG * TX * TY)   // 6144
#define NTHREADS 256
#define HTASKS (IN_H * 4)          // 296

// dynamic smem layout (bytes):
//  p_s  : [0,            12728)   74*43 floats
//  t_s  : [12728,        25456)
//  hc4  : [25456,        63344)   74*32 ulonglong2, swizzled cols
//  hcE  : [63344,        73112)   74*33 floats
#define SMEM_TOTAL 73112

typedef unsigned long long u64;

__device__ __align__(16) float g_partials[NBLOCKS];
__device__ unsigned int g_count;   // zero-init; reset by last block each run

__device__ __forceinline__ u64 pack2(float x, float y) {
    u64 r; asm("mov.b64 %0, {%1,%2};" : "=l"(r) : "f"(x), "f"(y)); return r;
}
__device__ __forceinline__ float2 unpack2(u64 v) {
    float2 r; asm("mov.b64 {%0,%1}, %2;" : "=f"(r.x), "=f"(r.y) : "l"(v)); return r;
}
__device__ __forceinline__ void fma2(u64 &d, u64 a, u64 b) {
    asm("fma.rn.f32x2 %0, %1, %2, %0;" : "+l"(d) : "l"(a), "l"(b));
}
__device__ __forceinline__ u64 mul2(u64 a, u64 b) {
    u64 d; asm("mul.rn.f32x2 %0, %1, %2;" : "=l"(d) : "l"(a), "l"(b)); return d;
}

__global__ __launch_bounds__(NTHREADS, 2) void ssim_fused_kernel(
    const float* __restrict__ pred,
    const float* __restrict__ target,
    const float* __restrict__ window,
    float* __restrict__ out)
{
    extern __shared__ float smem_f[];
    float*      p_s = smem_f;
    float*      t_s = smem_f + IN_H * PS;
    ulonglong2* hc4 = (ulonglong2*)(smem_f + 2 * IN_H * PS);
    float*      hcE = (float*)((char*)smem_f + 63344);
    __shared__ float wsum[NTHREADS / 32];
    __shared__ int   s_is_last;

    const int tid = threadIdx.x;
    const int img = blockIdx.z;
    const int x0 = blockIdx.x * TW;
    const int y0 = blockIdx.y * TH;

    const float* p_base = pred   + (size_t)img * (IMG_H * IMG_W);
    const float* t_base = target + (size_t)img * (IMG_H * IMG_W);

    // 1D gaussian from 2D window: g_i = w[5][i] * rsqrt(w[5][5])
    float gs[11];
    u64   gg[11];
    {
        float inv = rsqrtf(window[5 * 11 + 5]);
        #pragma unroll
        for (int i = 0; i < 11; i++) {
            gs[i] = window[5 * 11 + i] * inv;
            gg[i] = pack2(gs[i], gs[i]);
        }
    }

    // ---- Load tile + halo (zero pad) into separate p/t planes ----
    for (int idx = tid; idx < IN_H * IN_W; idx += NTHREADS) {
        int ly = idx / IN_W;
        int lx = idx - ly * IN_W;
        int gx = x0 + lx - HALO;
        int gy = y0 + ly - HALO;
        float p = 0.f, t = 0.f;
        if ((unsigned)gx < IMG_W && (unsigned)gy < IMG_H) {
            p = __ldg(p_base + gy * IMG_W + gx);
            t = __ldg(t_base + gy * IMG_W + gx);
        }
        p_s[ly * PS + lx] = p;
        t_s[ly * PS + lx] = t;
    }
    __syncthreads();

    // ---- Horizontal pass: register sliding, 8 outputs/task, packed FMA ----
    for (int task = tid; task < HTASKS; task += NTHREADS) {
        const int r  = task >> 2;
        const int c0 = (task & 3) * 8;
        const float* pr = p_s + r * PS + c0;
        const float* tr = t_s + r * PS + c0;

        u64 aA[8], aB[8];
        float aC[8];
        #pragma unroll
        for (int j = 0; j < 8; j++) { aA[j] = 0ull; aB[j] = 0ull; aC[j] = 0.f; }

        #pragma unroll
        for (int i = 0; i < 18; i++) {
            float p = pr[i];
            float t = tr[i];
            u64 v  = pack2(p, t);         // (p, t)
            u64 v2 = mul2(v, v);          // (p^2, t^2)
            float pt = p * t;
            #pragma unroll
            for (int j = 0; j < 8; j++) {
                int k = i - j;            // compile-time after unroll
                if (k >= 0 && k < 11) {
                    fma2(aA[j], gg[k], v);
                    fma2(aB[j], gg[k], v2);
                    aC[j] += gs[k] * pt;
                }
            }
        }

        const int s = r & 7;
        #pragma unroll
        for (int j = 0; j < 8; j++) {
            int csw = (c0 + j) ^ s;       // bank swizzle for 128-bit accesses
            hc4[r * 32 + csw] = make_ulonglong2(aA[j], aB[j]);
            hcE[r * 33 + c0 + j] = aC[j];
        }
    }
    __syncthreads();

    // ---- Vertical pass + SSIM: thread owns col c, 8 rows; 18 sliding loads ----
    const int c  = tid & 31;
    const int r0 = (tid >> 5) * 8;        // 8 warps * 8 rows = 64

    u64 aMu[8], aSg[8];
    float aPt[8];
    #pragma unroll
    for (int j = 0; j < 8; j++) { aMu[j] = 0ull; aSg[j] = 0ull; aPt[j] = 0.f; }

    #pragma unroll
    for (int rr = 0; rr < 18; rr++) {
        int ra = r0 + rr;
        ulonglong2 u = hc4[ra * 32 + (c ^ (ra & 7))];
        float hE = hcE[ra * 33 + c];
        #pragma unroll
        for (int j = 0; j < 8; j++) {
            int k = rr - j;
            if (k >= 0 && k < 11) {
                fma2(aMu[j], gg[k], u.x);   // (mu1, mu2)
                fma2(aSg[j], gg[k], u.y);   // (E[p^2], E[t^2])
                aPt[j] += gs[k] * hE;       // E[pt]
            }
        }
    }

    const float C1 = 1e-4f;
    const float C2 = 9e-4f;
    float local = 0.f;
    #pragma unroll
    for (int j = 0; j < 8; j++) {
        float2 mu = unpack2(aMu[j]);
        float2 sq = unpack2(aSg[j]);
        float mu12 = mu.x * mu.y;
        float mu1s = mu.x * mu.x;
        float mu2s = mu.y * mu.y;
        float num  = (2.f * mu12 + C1) * (2.f * (aPt[j] - mu12) + C2);
        float den  = (mu1s + mu2s + C1) *
                     ((sq.x - mu1s) + (sq.y - mu2s) + C2);
        local += __fdividef(num, den);
    }

    // ---- Deterministic block reduction ----
    #pragma unroll
    for (int off = 16; off; off >>= 1)
        local += __shfl_down_sync(0xffffffffu, local, off);
    if ((tid & 31) == 0) wsum[tid >> 5] = local;
    __syncthreads();
    if (tid < 8) {
        float v = wsum[tid];
        #pragma unroll
        for (int off = 4; off; off >>= 1)
            v += __shfl_down_sync(0x000000ffu, v, off);
        if (tid == 0) {
            int bidx = (blockIdx.z * TY + blockIdx.y) * TX + blockIdx.x;
            g_partials[bidx] = v;
        }
    }

    // ---- Last-block-done grid reduction (deterministic, resets counter) ----
    if (tid == 0) {
        __threadfence();
        unsigned old = atomicAdd(&g_count, 1u);
        s_is_last = (old == (unsigned)(NBLOCKS - 1));
    }
    __syncthreads();
    if (s_is_last) {
        __threadfence();
        double s = 0.0;
        const float4* p4 = (const float4*)g_partials;
        #pragma unroll
        for (int i = 0; i < NBLOCKS / 4 / NTHREADS; i++) {  // 6 iters
            float4 v = __ldcg(&p4[tid + i * NTHREADS]);
            s += (double)v.x + (double)v.y + (double)v.z + (double)v.w;
        }
        #pragma unroll
        for (int off = 16; off; off >>= 1)
            s += __shfl_down_sync(0xffffffffu, s, off);
        __shared__ double dsum[8];
        if ((tid & 31) == 0) dsum[tid >> 5] = s;
        __syncthreads();
        if (tid < 8) {
            double t = dsum[tid];
            #pragma unroll
            for (int off = 4; off; off >>= 1)
                t += __shfl_down_sync(0x000000ffu, t, off);
            if (tid == 0) {
                out[0] = (float)(1.0 - t / ((double)NIMG * IMG_H * IMG_W));
                g_count = 0;   // reset for next graph replay
            }
        }
    }
}

extern "C" void kernel_launch(void* const* d_in, const int* in_sizes, int n_in,
                              void* d_out, int out_size)
{
    (void)in_sizes; (void)n_in; (void)out_size;
    const float* pred   = (const float*)d_in[0];
    const float* target = (const float*)d_in[1];
    const float* window = (const float*)d_in[2];

    static int attr_set = 0;
    if (!attr_set) {
        cudaFuncSetAttribute(ssim_fused_kernel,
                             cudaFuncAttributeMaxDynamicSharedMemorySize,
                             SMEM_TOTAL);
        attr_set = 1;
    }

    dim3 grid(TX, TY, NIMG);
    ssim_fused_kernel<<<grid, NTHREADS, SMEM_TOTAL>>>(pred, target, window,
                                                      (float*)d_out);
}

// round 4
// speedup vs baseline: 1.4628x; 1.4628x over previous
#include <cuda_runtime.h>

// SSIM loss — separable 11-tap Gaussian, fused single-kernel.
// pred/target: [64,3,256,256] f32; window = outer(g,g); out scalar f32.

#define TW 32
#define TH 64
#define HALO 5
#define IN_W 42          // TW + 10
#define IN_H 74          // TH + 10
#define PS 43            // p/t smem row stride (floats)
#define IMG_H 256
#define IMG_W 256
#define NIMG 192
#define TX 8
#define TY 4
#define NBLOCKS (NIMG * TX * TY)   // 6144
#define NTHREADS 256
#define HTASKS (IN_H * 8)          // 592: 8 chunks of 4 cols per row

// dynamic smem layout (bytes):
//  p_s  : [0,     12728)   74*43 floats
//  t_s  : [12728, 25456)
//  hc4  : [25456, 63344)   74*32 ulonglong2, cols swizzled c^((c>>3)&3)
//  hcE  : [63344, 73112)   74*33 floats
#define SMEM_TOTAL 73112

typedef unsigned long long u64;

__device__ __align__(16) float g_partials[NBLOCKS];
__device__ unsigned int g_count;

__device__ __forceinline__ u64 pack2(float x, float y) {
    u64 r; asm("mov.b64 %0, {%1,%2};" : "=l"(r) : "f"(x), "f"(y)); return r;
}
__device__ __forceinline__ float2 unpack2(u64 v) {
    float2 r; asm("mov.b64 {%0,%1}, %2;" : "=f"(r.x), "=f"(r.y) : "l"(v)); return r;
}
__device__ __forceinline__ void fma2(u64 &d, u64 a, u64 b) {
    asm("fma.rn.f32x2 %0, %1, %2, %0;" : "+l"(d) : "l"(a), "l"(b));
}
__device__ __forceinline__ u64 mul2(u64 a, u64 b) {
    u64 d; asm("mul.rn.f32x2 %0, %1, %2;" : "=l"(d) : "l"(a), "l"(b)); return d;
}

__global__ __launch_bounds__(NTHREADS, 2) void ssim_fused_kernel(
    const float* __restrict__ pred,
    const float* __restrict__ target,
    const float* __restrict__ window,
    float* __restrict__ out)
{
    extern __shared__ float smem_f[];
    float*      p_s = smem_f;
    float*      t_s = smem_f + IN_H * PS;
    ulonglong2* hc4 = (ulonglong2*)(smem_f + 2 * IN_H * PS);
    float*      hcE = (float*)((char*)smem_f + 63344);
    __shared__ float wsum[NTHREADS / 32];
    __shared__ int   s_is_last;

    const int tid = threadIdx.x;
    const int img = blockIdx.z;
    const int x0 = blockIdx.x * TW;
    const int y0 = blockIdx.y * TH;

    const float* p_base = pred   + (size_t)img * (IMG_H * IMG_W);
    const float* t_base = target + (size_t)img * (IMG_H * IMG_W);

    // Symmetric 1D gaussian: g_i = w[5][i]*rsqrt(w[5][5]); g[k]==g[10-k]
    float gs6[6];
    u64   gg6[6];
    {
        float inv = rsqrtf(window[5 * 11 + 5]);
        #pragma unroll
        for (int i = 0; i < 6; i++) {
            gs6[i] = window[5 * 11 + i] * inv;
            gg6[i] = pack2(gs6[i], gs6[i]);
        }
    }

    // ---- Stage tile + halo (zero pad) into p/t planes ----
    #pragma unroll 1
    for (int idx = tid; idx < IN_H * IN_W; idx += NTHREADS) {
        int ly = idx / IN_W;
        int lx = idx - ly * IN_W;
        int gx = x0 + lx - HALO;
        int gy = y0 + ly - HALO;
        float p = 0.f, t = 0.f;
        if ((unsigned)gx < IMG_W && (unsigned)gy < IMG_H) {
            p = __ldg(p_base + gy * IMG_W + gx);
            t = __ldg(t_base + gy * IMG_W + gx);
        }
        p_s[ly * PS + lx] = p;
        t_s[ly * PS + lx] = t;
    }
    __syncthreads();

    // ---- Horizontal pass: 4 outputs/task, 14 sliding loads, packed FMA ----
    #pragma unroll 1
    for (int task = tid; task < HTASKS; task += NTHREADS) {
        const int r  = task >> 3;          // row (quarter-warp = 1 row)
        const int c0 = (task & 7) * 4;     // 8 chunks of 4 cols
        const float* pr = p_s + r * PS + c0;
        const float* tr = t_s + r * PS + c0;

        u64 aA[4], aB[4];
        float aC[4];
        #pragma unroll
        for (int j = 0; j < 4; j++) { aA[j] = 0ull; aB[j] = 0ull; aC[j] = 0.f; }

        #pragma unroll
        for (int i = 0; i < 14; i++) {
            float p = pr[i];
            float t = tr[i];
            u64 v  = pack2(p, t);          // (p, t)
            u64 v2 = mul2(v, v);           // (p^2, t^2)
            float pt = p * t;
            #pragma unroll
            for (int j = 0; j < 4; j++) {
                int k = i - j;             // compile-time after unroll
                if (k >= 0 && k < 11) {
                    int kk = (k < 6) ? k : 10 - k;   // symmetric coeff
                    fma2(aA[j], gg6[kk], v);
                    fma2(aB[j], gg6[kk], v2);
                    aC[j] += gs6[kk] * pt;
                }
            }
        }

        #pragma unroll
        for (int j = 0; j < 4; j++) {
            int c   = c0 + j;
            int csw = c ^ ((c >> 3) & 3);  // conflict-free both directions
            hc4[r * 32 + csw] = make_ulonglong2(aA[j], aB[j]);
            hcE[r * 33 + c]   = aC[j];
        }
    }
    __syncthreads();

    // ---- Vertical pass + SSIM: thread owns col c, 8 rows; 18 sliding loads ----
    const int c   = tid & 31;
    const int csw = c ^ ((c >> 3) & 3);    // loop-invariant now
    const int r0  = (tid >> 5) * 8;        // 8 warps * 8 rows = 64

    u64 aMu[8], aSg[8];
    float aPt[8];
    #pragma unroll
    for (int j = 0; j < 8; j++) { aMu[j] = 0ull; aSg[j] = 0ull; aPt[j] = 0.f; }

    #pragma unroll
    for (int rr = 0; rr < 18; rr++) {
        int ra = r0 + rr;
        ulonglong2 u = hc4[ra * 32 + csw];
        float hE = hcE[ra * 33 + c];
        #pragma unroll
        for (int j = 0; j < 8; j++) {
            int k = rr - j;
            if (k >= 0 && k < 11) {
                int kk = (k < 6) ? k : 10 - k;
                fma2(aMu[j], gg6[kk], u.x);   // (mu1, mu2)
                fma2(aSg[j], gg6[kk], u.y);   // (E[p^2], E[t^2])
                aPt[j] += gs6[kk] * hE;       // E[pt]
            }
        }
    }

    const float C1 = 1e-4f;
    const float C2 = 9e-4f;
    float local = 0.f;
    #pragma unroll
    for (int j = 0; j < 8; j++) {
        float2 mu = unpack2(aMu[j]);
        float2 sq = unpack2(aSg[j]);
        float mu12 = mu.x * mu.y;
        float mu1s = mu.x * mu.x;
        float mu2s = mu.y * mu.y;
        float num  = (2.f * mu12 + C1) * (2.f * (aPt[j] - mu12) + C2);
        float den  = (mu1s + mu2s + C1) *
                     ((sq.x - mu1s) + (sq.y - mu2s) + C2);
        local += __fdividef(num, den);
    }

    // ---- Deterministic block reduction ----
    #pragma unroll
    for (int off = 16; off; off >>= 1)
        local += __shfl_down_sync(0xffffffffu, local, off);
    if ((tid & 31) == 0) wsum[tid >> 5] = local;
    __syncthreads();
    if (tid < 8) {
        float v = wsum[tid];
        #pragma unroll
        for (int off = 4; off; off >>= 1)
            v += __shfl_down_sync(0x000000ffu, v, off);
        if (tid == 0) {
            int bidx = (blockIdx.z * TY + blockIdx.y) * TX + blockIdx.x;
            g_partials[bidx] = v;
        }
    }

    // ---- Last-block-done grid reduction ----
    if (tid == 0) {
        __threadfence();
        unsigned old = atomicAdd(&g_count, 1u);
        s_is_last = (old == (unsigned)(NBLOCKS - 1));
    }
    __syncthreads();
    if (s_is_last) {
        __threadfence();
        double s = 0.0;
        const float4* p4 = (const float4*)g_partials;
        #pragma unroll
        for (int i = 0; i < NBLOCKS / 4 / NTHREADS; i++) {
            float4 v = __ldcg(&p4[tid + i * NTHREADS]);
            s += (double)v.x + (double)v.y + (double)v.z + (double)v.w;
        }
        #pragma unroll
        for (int off = 16; off; off >>= 1)
            s += __shfl_down_sync(0xffffffffu, s, off);
        __shared__ double dsum[8];
        if ((tid & 31) == 0) dsum[tid >> 5] = s;
        __syncthreads();
        if (tid < 8) {
            double t = dsum[tid];
            #pragma unroll
            for (int off = 4; off; off >>= 1)
                t += __shfl_down_sync(0x000000ffu, t, off);
            if (tid == 0) {
                out[0] = (float)(1.0 - t / ((double)NIMG * IMG_H * IMG_W));
                g_count = 0;
            }
        }
    }
}

extern "C" void kernel_launch(void* const* d_in, const int* in_sizes, int n_in,
                              void* d_out, int out_size)
{
    (void)in_sizes; (void)n_in; (void)out_size;
    const float* pred   = (const float*)d_in[0];
    const float* target = (const float*)d_in[1];
    const float* window = (const float*)d_in[2];

    static int attr_set = 0;
    if (!attr_set) {
        cudaFuncSetAttribute(ssim_fused_kernel,
                             cudaFuncAttributeMaxDynamicSharedMemorySize,
                             SMEM_TOTAL);
        attr_set = 1;
    }

    dim3 grid(TX, TY, NIMG);
    ssim_fused_kernel<<<grid, NTHREADS, SMEM_TOTAL>>>(pred, target, window,
                                                      (float*)d_out);
}

// round 5
// speedup vs baseline: 2.0432x; 1.3968x over previous
#include <cuda_runtime.h>

// SSIM loss — separable 11-tap Gaussian, fused single-kernel.
// H-pass reads global directly (no staging); smem holds only h-conv fields.
// pred/target: [64,3,256,256] f32; window = outer(g,g); out scalar f32.

#define TW 32
#define TH 64
#define HALO 5
#define IN_H 74          // TH + 10
#define IMG_H 256
#define IMG_W 256
#define NIMG 192
#define TX 8
#define TY 4
#define NBLOCKS (NIMG * TX * TY)   // 6144
#define NTHREADS 256
#define HTASKS (IN_H * 8)          // 592: 8 chunks of 4 cols per row

// dynamic smem (bytes):
//  hc4 : [0,     37888)   74*32 ulonglong2 {(E p,E t),(E p2,E t2)}, cols swizzled
//  hcE : [37888, 47656)   74*33 floats  (E pt)
#define HC_E_OFF 37888
#define SMEM_TOTAL 47664

typedef unsigned long long u64;

__device__ __align__(16) float g_partials[NBLOCKS];
__device__ unsigned int g_count;

__device__ __forceinline__ u64 pack2(float x, float y) {
    u64 r; asm("mov.b64 %0, {%1,%2};" : "=l"(r) : "f"(x), "f"(y)); return r;
}
__device__ __forceinline__ float2 unpack2(u64 v) {
    float2 r; asm("mov.b64 {%0,%1}, %2;" : "=f"(r.x), "=f"(r.y) : "l"(v)); return r;
}
__device__ __forceinline__ void fma2(u64 &d, u64 a, u64 b) {
    asm("fma.rn.f32x2 %0, %1, %2, %0;" : "+l"(d) : "l"(a), "l"(b));
}
__device__ __forceinline__ u64 mul2(u64 a, u64 b) {
    u64 d; asm("mul.rn.f32x2 %0, %1, %2;" : "=l"(d) : "l"(a), "l"(b)); return d;
}

__global__ __launch_bounds__(NTHREADS, 4) void ssim_fused_kernel(
    const float* __restrict__ pred,
    const float* __restrict__ target,
    const float* __restrict__ window,
    float* __restrict__ out)
{
    extern __shared__ float smem_f[];
    ulonglong2* hc4 = (ulonglong2*)smem_f;
    float*      hcE = (float*)((char*)smem_f + HC_E_OFF);
    __shared__ float wsum[NTHREADS / 32];
    __shared__ int   s_is_last;

    const int tid = threadIdx.x;
    const int img = blockIdx.z;
    const int x0 = blockIdx.x * TW;
    const int y0 = blockIdx.y * TH;

    const float* p_base = pred   + (size_t)img * (IMG_H * IMG_W);
    const float* t_base = target + (size_t)img * (IMG_H * IMG_W);

    // Symmetric 1D gaussian: g_i = w[5][i]*rsqrt(w[5][5]); g[k]==g[10-k].
    // Scalar value is the low half of the packed pair (no separate regs).
    u64 gg6[6];
    {
        float inv = rsqrtf(window[5 * 11 + 5]);
        #pragma unroll
        for (int i = 0; i < 6; i++) {
            float g = window[5 * 11 + i] * inv;
            gg6[i] = pack2(g, g);
        }
    }

    // ---- Horizontal pass straight from global: 4 outputs/task, 14 loads ----
    #pragma unroll 1
    for (int task = tid; task < HTASKS; task += NTHREADS) {
        const int r   = task >> 3;           // hc row (quarter-warp = 1 row)
        const int c0  = (task & 7) * 4;      // 8 chunks of 4 cols
        const int gy  = y0 + r - HALO;
        const int gx0 = x0 + c0 - HALO;
        const bool vy = (unsigned)gy < (unsigned)IMG_H;
        const float* prow = p_base + gy * IMG_W;   // never deref when !vy
        const float* trow = t_base + gy * IMG_W;

        u64 aA[4], aB[4];
        float aC[4];
        #pragma unroll
        for (int j = 0; j < 4; j++) { aA[j] = 0ull; aB[j] = 0ull; aC[j] = 0.f; }

        #pragma unroll
        for (int i = 0; i < 14; i++) {
            int gx = gx0 + i;
            float p = 0.f, t = 0.f;
            if (vy && (unsigned)gx < (unsigned)IMG_W) {
                p = __ldg(prow + gx);
                t = __ldg(trow + gx);
            }
            u64 v  = pack2(p, t);            // (p, t)
            u64 v2 = mul2(v, v);             // (p^2, t^2)
            float pt = p * t;
            #pragma unroll
            for (int j = 0; j < 4; j++) {
                int k = i - j;               // compile-time after unroll
                if (k >= 0 && k < 11) {
                    int kk = (k < 6) ? k : 10 - k;
                    fma2(aA[j], gg6[kk], v);
                    fma2(aB[j], gg6[kk], v2);
                    aC[j] += unpack2(gg6[kk]).x * pt;
                }
            }
        }

        #pragma unroll
        for (int j = 0; j < 4; j++) {
            int c   = c0 + j;
            int csw = c ^ ((c >> 3) & 3);    // conflict-free store & load
            hc4[r * 32 + csw] = make_ulonglong2(aA[j], aB[j]);
            hcE[r * 33 + c]   = aC[j];
        }
    }
    __syncthreads();

    // ---- Vertical pass + SSIM: thread owns col c, 8 rows; 18 sliding loads ----
    const int c   = tid & 31;
    const int csw = c ^ ((c >> 3) & 3);      // loop-invariant
    const int r0  = (tid >> 5) * 8;          // 8 warps * 8 rows = 64

    u64 aMu[8], aSg[8];
    float aPt[8];
    #pragma unroll
    for (int j = 0; j < 8; j++) { aMu[j] = 0ull; aSg[j] = 0ull; aPt[j] = 0.f; }

    #pragma unroll
    for (int rr = 0; rr < 18; rr++) {
        int ra = r0 + rr;
        ulonglong2 u = hc4[ra * 32 + csw];
        float hE = hcE[ra * 33 + c];
        #pragma unroll
        for (int j = 0; j < 8; j++) {
            int k = rr - j;
            if (k >= 0 && k < 11) {
                int kk = (k < 6) ? k : 10 - k;
                fma2(aMu[j], gg6[kk], u.x);   // (mu1, mu2)
                fma2(aSg[j], gg6[kk], u.y);   // (E[p^2], E[t^2])
                aPt[j] += unpack2(gg6[kk]).x * hE;
            }
        }
    }

    const float C1 = 1e-4f;
    const float C2 = 9e-4f;
    float local = 0.f;
    #pragma unroll
    for (int j = 0; j < 8; j++) {
        float2 mu = unpack2(aMu[j]);
        float2 sq = unpack2(aSg[j]);
        float mu12 = mu.x * mu.y;
        float mu1s = mu.x * mu.x;
        float mu2s = mu.y * mu.y;
        float num  = (2.f * mu12 + C1) * (2.f * (aPt[j] - mu12) + C2);
        float den  = (mu1s + mu2s + C1) *
                     ((sq.x - mu1s) + (sq.y - mu2s) + C2);
        local += __fdividef(num, den);
    }

    // ---- Deterministic block reduction ----
    #pragma unroll
    for (int off = 16; off; off >>= 1)
        local += __shfl_down_sync(0xffffffffu, local, off);
    if ((tid & 31) == 0) wsum[tid >> 5] = local;
    __syncthreads();
    if (tid < 8) {
        float v = wsum[tid];
        #pragma unroll
        for (int off = 4; off; off >>= 1)
            v += __shfl_down_sync(0x000000ffu, v, off);
        if (tid == 0) {
            int bidx = (blockIdx.z * TY + blockIdx.y) * TX + blockIdx.x;
            g_partials[bidx] = v;
        }
    }

    // ---- Last-block-done grid reduction ----
    if (tid == 0) {
        __threadfence();
        unsigned old = atomicAdd(&g_count, 1u);
        s_is_last = (old == (unsigned)(NBLOCKS - 1));
    }
    __syncthreads();
    if (s_is_last) {
        __threadfence();
        double s = 0.0;
        const float4* p4 = (const float4*)g_partials;
        #pragma unroll
        for (int i = 0; i < NBLOCKS / 4 / NTHREADS; i++) {
            float4 v = __ldcg(&p4[tid + i * NTHREADS]);
            s += (double)v.x + (double)v.y + (double)v.z + (double)v.w;
        }
        #pragma unroll
        for (int off = 16; off; off >>= 1)
            s += __shfl_down_sync(0xffffffffu, s, off);
        __shared__ double dsum[8];
        if ((tid & 31) == 0) dsum[tid >> 5] = s;
        __syncthreads();
        if (tid < 8) {
            double t = dsum[tid];
            #pragma unroll
            for (int off = 4; off; off >>= 1)
                t += __shfl_down_sync(0x000000ffu, t, off);
            if (tid == 0) {
                out[0] = (float)(1.0 - t / ((double)NIMG * IMG_H * IMG_W));
                g_count = 0;
            }
        }
    }
}

extern "C" void kernel_launch(void* const* d_in, const int* in_sizes, int n_in,
                              void* d_out, int out_size)
{
    (void)in_sizes; (void)n_in; (void)out_size;
    const float* pred   = (const float*)d_in[0];
    const float* target = (const float*)d_in[1];
    const float* window = (const float*)d_in[2];

    dim3 grid(TX, TY, NIMG);
    ssim_fused_kernel<<<grid, NTHREADS, SMEM_TOTAL>>>(pred, target, window,
                                                      (float*)d_out);
}

// round 7
// speedup vs baseline: 2.3128x; 1.1320x over previous
#include <cuda_runtime.h>

// SSIM loss — separable 11-tap Gaussian, fused single-kernel.
// H-pass reads global directly; x-interior blocks use float4 loads.
// pred/target: [64,3,256,256] f32; window = outer(g,g); out scalar f32.

#define TW 32
#define TH 64
#define HALO 5
#define IN_H 74          // TH + 10
#define IMG_H 256
#define IMG_W 256
#define NIMG 192
#define TX 8
#define TY 4
#define NBLOCKS (NIMG * TX * TY)   // 6144
#define NTHREADS 256
#define HTASKS (IN_H * 8)          // 592: 8 chunks of 4 cols per row

// dynamic smem (bytes):
//  hc4 : [0,     37888)   74*32 ulonglong2 {(E p,E t),(E p2,E t2)}, swizzled cols
//  hcE : [37888, 47656)   74*33 floats  (E pt)
#define HC_E_OFF 37888
#define SMEM_TOTAL 47664

typedef unsigned long long u64;

__device__ __align__(16) float g_partials[NBLOCKS];
__device__ unsigned int g_count;

__device__ __forceinline__ u64 pack2(float x, float y) {
    u64 r; asm("mov.b64 %0, {%1,%2};" : "=l"(r) : "f"(x), "f"(y)); return r;
}
__device__ __forceinline__ float2 unpack2(u64 v) {
    float2 r; asm("mov.b64 {%0,%1}, %2;" : "=f"(r.x), "=f"(r.y) : "l"(v)); return r;
}
__device__ __forceinline__ void fma2(u64 &d, u64 a, u64 b) {
    asm("fma.rn.f32x2 %0, %1, %2, %0;" : "+l"(d) : "l"(a), "l"(b));
}
__device__ __forceinline__ u64 mul2(u64 a, u64 b) {
    u64 d; asm("mul.rn.f32x2 %0, %1, %2;" : "=l"(d) : "l"(a), "l"(b)); return d;
}

__global__ __launch_bounds__(NTHREADS, 4) void ssim_fused_kernel(
    const float* __restrict__ pred,
    const float* __restrict__ target,
    const float* __restrict__ window,
    float* __restrict__ out)
{
    extern __shared__ float smem_f[];
    ulonglong2* hc4 = (ulonglong2*)smem_f;
    float*      hcE = (float*)((char*)smem_f + HC_E_OFF);
    __shared__ float wsum[NTHREADS / 32];
    __shared__ int   s_is_last;

    const int tid = threadIdx.x;
    const int img = blockIdx.z;
    const int x0 = blockIdx.x * TW;
    const int y0 = blockIdx.y * TH;

    const float* p_base = pred   + (size_t)img * (IMG_H * IMG_W);
    const float* t_base = target + (size_t)img * (IMG_H * IMG_W);

    // Symmetric 1D gaussian: g_i = w[5][i]*rsqrt(w[5][5]); g[k]==g[10-k].
    float gs6[6];
    u64   gg6[6];
    {
        float inv = rsqrtf(window[5 * 11 + 5]);
        #pragma unroll
        for (int i = 0; i < 6; i++) {
            gs6[i] = window[5 * 11 + i] * inv;
            gg6[i] = pack2(gs6[i], gs6[i]);
        }
    }

    const bool edge_x = (blockIdx.x == 0) || (blockIdx.x == TX - 1);

    // ---- Horizontal pass: 4 outputs/task; fast path = 5 float4 loads/array ----
    if (!edge_x) {
        #pragma unroll 1
        for (int task = tid; task < HTASKS; task += NTHREADS) {
            const int r  = task >> 3;
            const int c0 = (task & 7) * 4;
            const int gy = y0 + r - HALO;

            u64 aA[4], aB[4];
            float aC[4];
            #pragma unroll
            for (int j = 0; j < 4; j++) { aA[j] = 0ull; aB[j] = 0ull; aC[j] = 0.f; }

            if ((unsigned)gy < (unsigned)IMG_H) {
                // aligned: x0+c0-8 is a multiple of 4 (16B)
                const float4* pv = (const float4*)(p_base + gy * IMG_W + x0 + c0 - 8);
                const float4* tv = (const float4*)(t_base + gy * IMG_W + x0 + c0 - 8);
                #pragma unroll
                for (int m = 0; m < 5; m++) {
                    float4 P = __ldg(pv + m);
                    float4 T = __ldg(tv + m);
                    float pa[4] = {P.x, P.y, P.z, P.w};
                    float ta[4] = {T.x, T.y, T.z, T.w};
                    #pragma unroll
                    for (int e = 0; e < 4; e++) {
                        const int i = m * 4 + e - 3;   // window index
                        if (i < 0 || i > 13) continue;
                        float p = pa[e], t = ta[e];
                        u64 v  = pack2(p, t);
                        u64 v2 = mul2(v, v);
                        float pt = p * t;
                        #pragma unroll
                        for (int j = 0; j < 4; j++) {
                            int k = i - j;
                            if (k >= 0 && k < 11) {
                                int kk = (k < 6) ? k : 10 - k;
                                fma2(aA[j], gg6[kk], v);
                                fma2(aB[j], gg6[kk], v2);
                                aC[j] += gs6[kk] * pt;
                            }
                        }
                    }
                }
            }

            #pragma unroll
            for (int j = 0; j < 4; j++) {
                int c   = c0 + j;
                int csw = c ^ ((c >> 3) & 3);
                hc4[r * 32 + csw] = make_ulonglong2(aA[j], aB[j]);
                hcE[r * 33 + c]   = aC[j];
            }
        }
    } else {
        #pragma unroll 1
        for (int task = tid; task < HTASKS; task += NTHREADS) {
            const int r   = task >> 3;
            const int c0  = (task & 7) * 4;
            const int gy  = y0 + r - HALO;
            const int gx0 = x0 + c0 - HALO;
            const bool vy = (unsigned)gy < (unsigned)IMG_H;
            const float* prow = p_base + gy * IMG_W;
            const float* trow = t_base + gy * IMG_W;

            u64 aA[4], aB[4];
            float aC[4];
            #pragma unroll
            for (int j = 0; j < 4; j++) { aA[j] = 0ull; aB[j] = 0ull; aC[j] = 0.f; }

            #pragma unroll
            for (int i = 0; i < 14; i++) {
                int gx = gx0 + i;
                float p = 0.f, t = 0.f;
                if (vy && (unsigned)gx < (unsigned)IMG_W) {
                    p = __ldg(prow + gx);
                    t = __ldg(trow + gx);
                }
                u64 v  = pack2(p, t);
                u64 v2 = mul2(v, v);
                float pt = p * t;
                #pragma unroll
                for (int j = 0; j < 4; j++) {
                    int k = i - j;
                    if (k >= 0 && k < 11) {
                        int kk = (k < 6) ? k : 10 - k;
                        fma2(aA[j], gg6[kk], v);
                        fma2(aB[j], gg6[kk], v2);
                        aC[j] += gs6[kk] * pt;
                    }
                }
            }

            #pragma unroll
            for (int j = 0; j < 4; j++) {
                int c   = c0 + j;
                int csw = c ^ ((c >> 3) & 3);
                hc4[r * 32 + csw] = make_ulonglong2(aA[j], aB[j]);
                hcE[r * 33 + c]   = aC[j];
            }
        }
    }
    __syncthreads();

    // ---- Vertical pass + SSIM: thread owns col c, 8 rows; 18 sliding loads ----
    const int c   = tid & 31;
    const int csw = c ^ ((c >> 3) & 3);
    const int r0  = (tid >> 5) * 8;        // 8 warps * 8 rows = 64

    u64 aMu[8], aSg[8];
    float aPt[8];
    #pragma unroll
    for (int j = 0; j < 8; j++) { aMu[j] = 0ull; aSg[j] = 0ull; aPt[j] = 0.f; }

    #pragma unroll
    for (int rr = 0; rr < 18; rr++) {
        int ra = r0 + rr;
        ulonglong2 u = hc4[ra * 32 + csw];
        float hE = hcE[ra * 33 + c];
        #pragma unroll
        for (int j = 0; j < 8; j++) {
            int k = rr - j;
            if (k >= 0 && k < 11) {
                int kk = (k < 6) ? k : 10 - k;
                fma2(aMu[j], gg6[kk], u.x);   // (mu1, mu2)
                fma2(aSg[j], gg6[kk], u.y);   // (E[p^2], E[t^2])
                aPt[j] += gs6[kk] * hE;       // E[pt]
            }
        }
    }

    const float C1 = 1e-4f;
    const float C2 = 9e-4f;
    float local = 0.f;
    #pragma unroll
    for (int j = 0; j < 8; j++) {
        float2 mu = unpack2(aMu[j]);
        float2 sq = unpack2(aSg[j]);
        float mu12 = mu.x * mu.y;
        float mu1s = mu.x * mu.x;
        float mu2s = mu.y * mu.y;
        float num  = (2.f * mu12 + C1) * (2.f * (aPt[j] - mu12) + C2);
        float den  = (mu1s + mu2s + C1) *
                     ((sq.x - mu1s) + (sq.y - mu2s) + C2);
        local += __fdividef(num, den);
    }

    // ---- Deterministic block reduction ----
    #pragma unroll
    for (int off = 16; off; off >>= 1)
        local += __shfl_down_sync(0xffffffffu, local, off);
    if ((tid & 31) == 0) wsum[tid >> 5] = local;
    __syncthreads();
    if (tid < 8) {
        float v = wsum[tid];
        #pragma unroll
        for (int off = 4; off; off >>= 1)
            v += __shfl_down_sync(0x000000ffu, v, off);
        if (tid == 0) {
            int bidx = (blockIdx.z * TY + blockIdx.y) * TX + blockIdx.x;
            g_partials[bidx] = v;
        }
    }

    // ---- Last-block-done grid reduction ----
    if (tid == 0) {
        __threadfence();
        unsigned old = atomicAdd(&g_count, 1u);
        s_is_last = (old == (unsigned)(NBLOCKS - 1));
    }
    __syncthreads();
    if (s_is_last) {
        __threadfence();
        double s = 0.0;
        const float4* p4 = (const float4*)g_partials;
        #pragma unroll
        for (int i = 0; i < NBLOCKS / 4 / NTHREADS; i++) {
            float4 v = __ldcg(&p4[tid + i * NTHREADS]);
            s += (double)v.x + (double)v.y + (double)v.z + (double)v.w;
        }
        #pragma unroll
        for (int off = 16; off; off >>= 1)
            s += __shfl_down_sync(0xffffffffu, s, off);
        __shared__ double dsum[8];
        if ((tid & 31) == 0) dsum[tid >> 5] = s;
        __syncthreads();
        if (tid < 8) {
            double t = dsum[tid];
            #pragma unroll
            for (int off = 4; off; off >>= 1)
                t += __shfl_down_sync(0x000000ffu, t, off);
            if (tid == 0) {
                out[0] = (float)(1.0 - t / ((double)NIMG * IMG_H * IMG_W));
                g_count = 0;
            }
        }
    }
}

extern "C" void kernel_launch(void* const* d_in, const int* in_sizes, int n_in,
                              void* d_out, int out_size)
{
    (void)in_sizes; (void)n_in; (void)out_size;
    const float* pred   = (const float*)d_in[0];
    const float* target = (const float*)d_in[1];
    const float* window = (const float*)d_in[2];

    dim3 grid(TX, TY, NIMG);
    ssim_fused_kernel<<<grid, NTHREADS, SMEM_TOTAL>>>(pred, target, window,
                                                      (float*)d_out);
}